// round 7
// baseline (speedup 1.0000x reference)
#include <cuda_runtime.h>
#include <cstdint>

#define N_NODES 50000
#define E_EDGES 800000
#define F 128
#define NB_SCAN 196              // ceil(50000/256)
#define HS_STRIDE 130            // floats per Hs row (even => 8B-aligned k-pairs)
#define KC 16                    // k-chunk for W smem staging

// ---- scratch (__device__ globals; allocation-free rule) ----
__device__ int   g_cnt[50176];       // per-node in-degree
__device__ int   g_start[50176];     // CSR offsets (arbitrary global order)
__device__ int   g_cursor[50176];    // atomic fill cursors
__device__ int   g_total;            // global base cursor for offsets
__device__ int2  g_ebuf[E_EDGES];    // bucketed edges: {src, bits(w+1)}
// W packed for FFMA2: ull slot u = chunk*1024 + pair*128 + j*16 + tx
//   where k = chunk*16 + pair*2 + sub, c = tx*8 + j; float idx = 2u + sub
__device__ unsigned long long g_wp[(F / 2) * F];

// fma.rn.f32x2: packed dual fp32 FMA (SASS FFMA2) — 2 FMAs per instruction
__device__ __forceinline__ void ffma2(unsigned long long& d,
                                      unsigned long long a,
                                      unsigned long long b) {
    asm("fma.rn.f32x2 %0, %1, %2, %0;" : "+l"(d) : "l"(a), "l"(b));
}

// ---------------------------------------------------------------------------
// K1: zero counters + pack W into FFMA2-friendly layout
// ---------------------------------------------------------------------------
__global__ void prep_kernel(const float* __restrict__ W) {
    int tid = blockIdx.x * blockDim.x + threadIdx.x;
    if (tid == 0) g_total = 0;
    if (tid < F * F) {
        int k = tid >> 7;            // 0..127
        int c = tid & 127;           // 0..127
        int chunk = k >> 4, pair = (k >> 1) & 7, sub = k & 1;
        int j = c & 7, tx = c >> 3;
        int u = chunk * 1024 + pair * 128 + j * 16 + tx;
        reinterpret_cast<float*>(g_wp)[2 * u + sub] = W[c * F + k]; // W^T[k][c]
    }
    for (int i = tid; i < 50176; i += gridDim.x * blockDim.x)
        g_cnt[i] = 0;
}

// ---------------------------------------------------------------------------
// K2: histogram of dst (int4 vectorized)
// ---------------------------------------------------------------------------
__global__ __launch_bounds__(256) void hist_kernel(const int* __restrict__ dst) {
    int t = blockIdx.x * blockDim.x + threadIdx.x;
    if (t * 4 >= E_EDGES) return;
    int4 d = reinterpret_cast<const int4*>(dst)[t];
    atomicAdd(&g_cnt[d.x], 1);
    atomicAdd(&g_cnt[d.y], 1);
    atomicAdd(&g_cnt[d.z], 1);
    atomicAdd(&g_cnt[d.w], 1);
}

// ---------------------------------------------------------------------------
// K3: CSR offsets. Local scan over 256 nodes + ONE atomicAdd for block base.
//     (segments need only per-node contiguity, not global node order)
// ---------------------------------------------------------------------------
__global__ __launch_bounds__(256) void offsets_kernel() {
    __shared__ int sh[256];
    __shared__ int base;
    int t = threadIdx.x;
    int idx = blockIdx.x * 256 + t;
    int v = (idx < N_NODES) ? g_cnt[idx] : 0;
    sh[t] = v;
    __syncthreads();
    for (int d = 1; d < 256; d <<= 1) {
        int add = (t >= d) ? sh[t - d] : 0;
        __syncthreads();
        sh[t] += add;
        __syncthreads();
    }
    if (t == 255) base = atomicAdd(&g_total, sh[255]);
    __syncthreads();
    if (idx < N_NODES) {
        int start = base + sh[t] - v;
        g_start[idx]  = start;
        g_cursor[idx] = start;
    }
}

// ---------------------------------------------------------------------------
// K4: bucket edges by dst (vectorized loads)
// ---------------------------------------------------------------------------
__global__ __launch_bounds__(256) void bucket_kernel(
    const float* __restrict__ weight,
    const int*   __restrict__ src,
    const int*   __restrict__ dst)
{
    int t = blockIdx.x * blockDim.x + threadIdx.x;
    if (t * 4 >= E_EDGES) return;
    int4   s = reinterpret_cast<const int4*>(src)[t];
    int4   d = reinterpret_cast<const int4*>(dst)[t];
    float4 w = reinterpret_cast<const float4*>(weight)[t];
    int p0 = atomicAdd(&g_cursor[d.x], 1);
    g_ebuf[p0] = make_int2(s.x, __float_as_int(w.x + 1.0f));
    int p1 = atomicAdd(&g_cursor[d.y], 1);
    g_ebuf[p1] = make_int2(s.y, __float_as_int(w.y + 1.0f));
    int p2 = atomicAdd(&g_cursor[d.z], 1);
    g_ebuf[p2] = make_int2(s.z, __float_as_int(w.z + 1.0f));
    int p3 = atomicAdd(&g_cursor[d.w], 1);
    g_ebuf[p3] = make_int2(s.w, __float_as_int(w.w + 1.0f));
}

// ---------------------------------------------------------------------------
// K5: fused aggregate + affine + FFMA2 GEMM + bias.
//   Block = 256 threads, 64 output rows.
//   Phase A: warp w gathers rows w*8..w*8+7 via CSR (MLP=4), h -> smem.
//   Phase B: packed-k fp32 GEMM: acc.lo accumulates even k, acc.hi odd k.
// ---------------------------------------------------------------------------
__global__ __launch_bounds__(256, 3) void fused_kernel(
    const float* __restrict__ feature,
    const float* __restrict__ selfw,
    const float* __restrict__ bvec,
    float*       __restrict__ out)
{
    __shared__ float              Hs[64 * HS_STRIDE];   // h rows [row][k]
    __shared__ unsigned long long Ws[(KC / 2) * 128];   // 1024 ull = 8KB chunk

    const int tid  = threadIdx.x;
    const int lane = tid & 31;
    const int warp = tid >> 5;
    const int Rbase = blockIdx.x * 64;
    const float4* f4 = reinterpret_cast<const float4*>(feature);

    // ---------------- Phase A: aggregation ----------------
#pragma unroll 1
    for (int rr = 0; rr < 8; rr++) {
        int rloc = warp * 8 + rr;
        int r = Rbase + rloc;
        int rc = r < N_NODES ? r : (N_NODES - 1);
        int beg = __ldg(&g_start[rc]);
        int cnt = (r < N_NODES) ? __ldg(&g_cnt[rc]) : 0;
        int end = beg + cnt;

        float4 a0 = make_float4(0.f, 0.f, 0.f, 0.f);
        float4 a1 = make_float4(0.f, 0.f, 0.f, 0.f);
        float4 a2 = make_float4(0.f, 0.f, 0.f, 0.f);
        float4 a3 = make_float4(0.f, 0.f, 0.f, 0.f);

        int i = beg;
        for (; i + 4 <= end; i += 4) {
            int2 e0 = g_ebuf[i], e1 = g_ebuf[i + 1];
            int2 e2 = g_ebuf[i + 2], e3 = g_ebuf[i + 3];
            float4 v0 = __ldg(f4 + e0.x * 32 + lane);
            float4 v1 = __ldg(f4 + e1.x * 32 + lane);
            float4 v2 = __ldg(f4 + e2.x * 32 + lane);
            float4 v3 = __ldg(f4 + e3.x * 32 + lane);
            float w0 = __int_as_float(e0.y), w1 = __int_as_float(e1.y);
            float w2 = __int_as_float(e2.y), w3 = __int_as_float(e3.y);
            a0.x = fmaf(w0, v0.x, a0.x); a0.y = fmaf(w0, v0.y, a0.y);
            a0.z = fmaf(w0, v0.z, a0.z); a0.w = fmaf(w0, v0.w, a0.w);
            a1.x = fmaf(w1, v1.x, a1.x); a1.y = fmaf(w1, v1.y, a1.y);
            a1.z = fmaf(w1, v1.z, a1.z); a1.w = fmaf(w1, v1.w, a1.w);
            a2.x = fmaf(w2, v2.x, a2.x); a2.y = fmaf(w2, v2.y, a2.y);
            a2.z = fmaf(w2, v2.z, a2.z); a2.w = fmaf(w2, v2.w, a2.w);
            a3.x = fmaf(w3, v3.x, a3.x); a3.y = fmaf(w3, v3.y, a3.y);
            a3.z = fmaf(w3, v3.z, a3.z); a3.w = fmaf(w3, v3.w, a3.w);
        }
        for (; i < end; i++) {
            int2 e0 = g_ebuf[i];
            float4 v0 = __ldg(f4 + e0.x * 32 + lane);
            float w0 = __int_as_float(e0.y);
            a0.x = fmaf(w0, v0.x, a0.x); a0.y = fmaf(w0, v0.y, a0.y);
            a0.z = fmaf(w0, v0.z, a0.z); a0.w = fmaf(w0, v0.w, a0.w);
        }

        float sw = __ldg(selfw + rc) + 1.0f;
        float4 fv = __ldg(f4 + rc * 32 + lane);
        float4 h;
        h.x = fmaf(fv.x, sw, (a0.x + a1.x) + (a2.x + a3.x));
        h.y = fmaf(fv.y, sw, (a0.y + a1.y) + (a2.y + a3.y));
        h.z = fmaf(fv.z, sw, (a0.z + a1.z) + (a2.z + a3.z));
        h.w = fmaf(fv.w, sw, (a0.w + a1.w) + (a2.w + a3.w));
        // 4 scalar stores (HS_STRIDE=130 breaks 16B alignment for float4)
        float* hrow = Hs + rloc * HS_STRIDE + lane * 4;
        hrow[0] = h.x; hrow[1] = h.y; hrow[2] = h.z; hrow[3] = h.w;
    }
    __syncthreads();

    // ---------------- Phase B: packed-k FFMA2 GEMM ----------------
    const int tx = tid & 15;   // cols tx*8 .. tx*8+7
    const int ty = tid >> 4;   // rows ty*4 .. ty*4+3

    unsigned long long acc[4][4];   // [row][colpair-slot]: lo=even-k, hi=odd-k
#pragma unroll
    for (int i = 0; i < 4; i++)
#pragma unroll
        for (int j = 0; j < 4; j++) acc[i][j] = 0ull;
    // NOTE: acc[i][j] slot j corresponds to output col tx*8 + j (j in 0..7 via
    // two banks below). We use acc2 layout [row][j8] flattened: need 8 cols ->
    // use two arrays to keep j 0..7:
    unsigned long long acc2[4][4];
#pragma unroll
    for (int i = 0; i < 4; i++)
#pragma unroll
        for (int j = 0; j < 4; j++) acc2[i][j] = 0ull;

#pragma unroll 1
    for (int kk = 0; kk < F; kk += KC) {
        // stage 8KB W chunk: 512 float4 across 256 threads
        {
            const float4* s4 = reinterpret_cast<const float4*>(
                g_wp + (kk >> 1) * 128);
            float4* d4 = reinterpret_cast<float4*>(Ws);
            d4[tid]       = s4[tid];
            d4[tid + 256] = s4[tid + 256];
        }
        __syncthreads();

#pragma unroll
        for (int p = 0; p < KC / 2; p++) {      // k-pair index within chunk
            // h pairs: contiguous {h_2k, h_2k+1} per row
            unsigned long long h2[4];
#pragma unroll
            for (int i = 0; i < 4; i++)
                h2[i] = *reinterpret_cast<const unsigned long long*>(
                    Hs + (ty * 4 + i) * HS_STRIDE + kk + 2 * p);
            // w pairs: conflict-free broadcast layout [p][j][tx]
            const unsigned long long* wrow = Ws + p * 128 + tx;
            unsigned long long w2[8];
#pragma unroll
            for (int j = 0; j < 8; j++)
                w2[j] = wrow[j * 16];
#pragma unroll
            for (int i = 0; i < 4; i++) {
                ffma2(acc[i][0],  h2[i], w2[0]);
                ffma2(acc[i][1],  h2[i], w2[1]);
                ffma2(acc[i][2],  h2[i], w2[2]);
                ffma2(acc[i][3],  h2[i], w2[3]);
                ffma2(acc2[i][0], h2[i], w2[4]);
                ffma2(acc2[i][1], h2[i], w2[5]);
                ffma2(acc2[i][2], h2[i], w2[6]);
                ffma2(acc2[i][3], h2[i], w2[7]);
            }
        }
        __syncthreads();
    }

    // epilogue: combine even/odd partials, add bias, store
    float4 b0 = *reinterpret_cast<const float4*>(bvec + tx * 8);
    float4 b1 = *reinterpret_cast<const float4*>(bvec + tx * 8 + 4);
#pragma unroll
    for (int i = 0; i < 4; i++) {
        int r = Rbase + ty * 4 + i;
        if (r < N_NODES) {
            float2 p0 = *reinterpret_cast<float2*>(&acc[i][0]);
            float2 p1 = *reinterpret_cast<float2*>(&acc[i][1]);
            float2 p2 = *reinterpret_cast<float2*>(&acc[i][2]);
            float2 p3 = *reinterpret_cast<float2*>(&acc[i][3]);
            float2 q0 = *reinterpret_cast<float2*>(&acc2[i][0]);
            float2 q1 = *reinterpret_cast<float2*>(&acc2[i][1]);
            float2 q2 = *reinterpret_cast<float2*>(&acc2[i][2]);
            float2 q3 = *reinterpret_cast<float2*>(&acc2[i][3]);
            float4 o0 = make_float4(p0.x + p0.y + b0.x, p1.x + p1.y + b0.y,
                                    p2.x + p2.y + b0.z, p3.x + p3.y + b0.w);
            float4 o1 = make_float4(q0.x + q0.y + b1.x, q1.x + q1.y + b1.y,
                                    q2.x + q2.y + b1.z, q3.x + q3.y + b1.w);
            *reinterpret_cast<float4*>(out + (size_t)r * F + tx * 8)     = o0;
            *reinterpret_cast<float4*>(out + (size_t)r * F + tx * 8 + 4) = o1;
        }
    }
}

// ---------------------------------------------------------------------------
// Launch. Inputs (metadata order):
//   0 feature [N,128] f32   1 self_weight [N,1] f32   2 weight [E] f32
//   3 src [E] i32           4 dst [E] i32             5 W [128,128] f32
//   6 b [128] f32           Output: [N,128] f32
// ---------------------------------------------------------------------------
extern "C" void kernel_launch(void* const* d_in, const int* in_sizes, int n_in,
                              void* d_out, int out_size)
{
    const float* feature = (const float*)d_in[0];
    const float* selfw   = (const float*)d_in[1];
    const float* weight  = (const float*)d_in[2];
    const int*   src     = (const int*)d_in[3];
    const int*   dst     = (const int*)d_in[4];
    const float* W       = (const float*)d_in[5];
    const float* bvec    = (const float*)d_in[6];
    float*       out     = (float*)d_out;

    const int edge_blocks = (E_EDGES / 4 + 255) / 256;  // 782
    const int gemm_blocks = (N_NODES + 63) / 64;        // 782

    prep_kernel<<<256, 256>>>(W);
    hist_kernel<<<edge_blocks, 256>>>(dst);
    offsets_kernel<<<NB_SCAN, 256>>>();
    bucket_kernel<<<edge_blocks, 256>>>(weight, src, dst);
    fused_kernel<<<gemm_blocks, 256>>>(feature, selfw, bvec, out);
}